// round 3
// baseline (speedup 1.0000x reference)
#include <cuda_runtime.h>

#define N_NODES 100000
#define N_EDGES 1250000
#define NGRAPH  256
#define HID     64
#define IN_DIM  7

#define SCAN_E  1024
#define SCAN_B  ((N_NODES + SCAN_E - 1) / SCAN_E)   // 98

// ---------------- scratch (device globals; no allocation allowed) ----------
__device__ float g_dinv[N_NODES];
__device__ int   g_deg[N_NODES];
__device__ int   g_rowptr[N_NODES + 1];
__device__ int   g_cursor[N_NODES];
__device__ int   g_csr[N_EDGES];
__device__ int   g_partials[SCAN_B];
__device__ int   g_gcnt[NGRAPH];
__device__ int   g_goff[NGRAPH + 1];
__device__ __align__(16) float g_bufA[N_NODES * HID];
__device__ __align__(16) float g_bufB[N_NODES * HID];

// ---------------- setup kernels -------------------------------------------
__global__ void k_zero() {
    int i = blockIdx.x * blockDim.x + threadIdx.x;
    if (i < N_NODES) g_deg[i] = 0;
    if (i < NGRAPH)  g_gcnt[i] = 0;
}

__global__ void k_deg(const int* __restrict__ ei) {
    int e = blockIdx.x * blockDim.x + threadIdx.x;
    if (e < N_EDGES) {
        int d = ei[N_EDGES + e];
        atomicAdd(&g_deg[d], 1);
    }
}

__global__ void k_dinv(const int* __restrict__ batch) {
    int i = blockIdx.x * blockDim.x + threadIdx.x;
    if (i < N_NODES) {
        g_dinv[i] = rsqrtf((float)(g_deg[i] + 1));   // +1 self-loop
        atomicAdd(&g_gcnt[batch[i]], 1);
    }
}

// exclusive scan of g_deg -> g_rowptr (block-local), partial sums to g_partials
__global__ void k_scan1() {
    __shared__ int wraw[8], wscan[8];
    int t = threadIdx.x, b = blockIdx.x;
    int base = b * SCAN_E + t * 4;
    int v0 = 0, v1 = 0, v2 = 0, v3 = 0;
    if (base + 0 < N_NODES) v0 = g_deg[base + 0];
    if (base + 1 < N_NODES) v1 = g_deg[base + 1];
    if (base + 2 < N_NODES) v2 = g_deg[base + 2];
    if (base + 3 < N_NODES) v3 = g_deg[base + 3];
    int ts = v0 + v1 + v2 + v3;
    int lane = t & 31, wid = t >> 5;
    int inc = ts;
    #pragma unroll
    for (int o = 1; o < 32; o <<= 1) {
        int y = __shfl_up_sync(0xffffffffu, inc, o);
        if (lane >= o) inc += y;
    }
    if (lane == 31) wraw[wid] = inc;
    __syncthreads();
    if (t < 8) {
        int w = wraw[t];
        #pragma unroll
        for (int o = 1; o < 8; o <<= 1) {
            int y = __shfl_up_sync(0xffu, w, o);
            if (t >= o) w += y;
        }
        wscan[t] = w;
    }
    __syncthreads();
    int ex = (wid ? wscan[wid - 1] : 0) + (inc - ts);
    if (base + 0 < N_NODES) g_rowptr[base + 0] = ex;  ex += v0;
    if (base + 1 < N_NODES) g_rowptr[base + 1] = ex;  ex += v1;
    if (base + 2 < N_NODES) g_rowptr[base + 2] = ex;  ex += v2;
    if (base + 3 < N_NODES) g_rowptr[base + 3] = ex;
    if (t == 0) g_partials[b] = wscan[7];
}

// single-thread scans: block partials (98) and graph counts (256)
__global__ void k_scan2() {
    int run = 0;
    for (int b = 0; b < SCAN_B; b++) { int x = g_partials[b]; g_partials[b] = run; run += x; }
    int r2 = 0;
    for (int g = 0; g < NGRAPH; g++) { g_goff[g] = r2; r2 += g_gcnt[g]; }
    g_goff[NGRAPH] = r2;
}

__global__ void k_scan3() {
    int i = blockIdx.x * blockDim.x + threadIdx.x;
    if (i < N_NODES) {
        int r = g_rowptr[i] + g_partials[i / SCAN_E];
        g_rowptr[i] = r;
        g_cursor[i] = r;
    }
    if (i == 0) g_rowptr[N_NODES] = N_EDGES;
}

__global__ void k_scatter(const int* __restrict__ ei) {
    int e = blockIdx.x * blockDim.x + threadIdx.x;
    if (e < N_EDGES) {
        int d = ei[N_EDGES + e];
        int p = atomicAdd(&g_cursor[d], 1);
        g_csr[p] = ei[e];
    }
}

// ---------------- layer kernels (fixed dataflow: x->A, agg A->B, gemm B->A) -
// layer1 GEMM: g_bufA[v] = dinv[v] * (x[v, 0:7] @ W1)   (warp per node)
__global__ void k_xw1(const float* __restrict__ x, const float* __restrict__ W1) {
    __shared__ float sW[IN_DIM * HID];
    int t = threadIdx.x;
    for (int i = t; i < IN_DIM * HID; i += 256) sW[i] = W1[i];
    __syncthreads();
    int w = blockIdx.x * 8 + (t >> 5);
    if (w >= N_NODES) return;
    int lane = t & 31;
    float xv = (lane < IN_DIM) ? x[w * IN_DIM + lane] : 0.f;
    float a0 = 0.f, a1 = 0.f;
    #pragma unroll
    for (int k = 0; k < IN_DIM; k++) {
        float xk = __shfl_sync(0xffffffffu, xv, k);
        a0 += xk * sW[k * HID + lane];
        a1 += xk * sW[k * HID + 32 + lane];
    }
    float s = g_dinv[w];
    g_bufA[w * HID + lane]      = a0 * s;
    g_bufA[w * HID + 32 + lane] = a1 * s;
}

// 64x64 GEMM tile: g_bufA = dinv[v] * (g_bufB[v] @ W), 64 nodes per block,
// register-blocked 4x4 per thread with float4 shared loads.
__global__ void __launch_bounds__(256) k_xw64(const float* __restrict__ W) {
    __shared__ __align__(16) float sA[64][68];  // sA[k][m] (transposed input tile)
    __shared__ __align__(16) float sW[64][68];  // sW[k][n]
    int t = threadIdx.x;
    int nb = blockIdx.x * 64;
    for (int i = t; i < 4096; i += 256) {
        int k = i >> 6, n = i & 63;
        sW[k][n] = W[i];
        int m = i >> 6, kk = i & 63;
        int node = nb + m;
        sA[kk][m] = (node < N_NODES) ? g_bufB[node * HID + kk] : 0.f;
    }
    __syncthreads();
    int tx = t & 15, ty = t >> 4;       // dims n0 = tx*4, nodes m0 = ty*4
    float acc[4][4] = {};
    #pragma unroll
    for (int k = 0; k < 64; k++) {
        float4 a = *(const float4*)&sA[k][ty * 4];
        float4 wv = *(const float4*)&sW[k][tx * 4];
        acc[0][0] += a.x * wv.x; acc[0][1] += a.x * wv.y; acc[0][2] += a.x * wv.z; acc[0][3] += a.x * wv.w;
        acc[1][0] += a.y * wv.x; acc[1][1] += a.y * wv.y; acc[1][2] += a.y * wv.z; acc[1][3] += a.y * wv.w;
        acc[2][0] += a.z * wv.x; acc[2][1] += a.z * wv.y; acc[2][2] += a.z * wv.z; acc[2][3] += a.z * wv.w;
        acc[3][0] += a.w * wv.x; acc[3][1] += a.w * wv.y; acc[3][2] += a.w * wv.z; acc[3][3] += a.w * wv.w;
    }
    #pragma unroll
    for (int m = 0; m < 4; m++) {
        int node = nb + ty * 4 + m;
        if (node < N_NODES) {
            float s = g_dinv[node];
            float4 r;
            r.x = acc[m][0] * s; r.y = acc[m][1] * s; r.z = acc[m][2] * s; r.w = acc[m][3] * s;
            *(float4*)&g_bufA[node * HID + tx * 4] = r;
        }
    }
}

// aggregation: g_bufB[v] = act( dinv[v]*(g_bufA[v] + sum_{CSR[v]} g_bufA[src]) + b )
__global__ void __launch_bounds__(256) k_agg(const float* __restrict__ bias, int do_relu) {
    int w = (blockIdx.x * blockDim.x + threadIdx.x) >> 5;
    if (w >= N_NODES) return;
    int lane = threadIdx.x & 31;
    int beg = g_rowptr[w], end = g_rowptr[w + 1];
    float a0 = g_bufA[w * HID + lane];
    float a1 = g_bufA[w * HID + 32 + lane];
    int e = beg;
    for (; e + 4 <= end; e += 4) {
        int u0 = g_csr[e], u1 = g_csr[e + 1], u2 = g_csr[e + 2], u3 = g_csr[e + 3];
        float b00 = g_bufA[u0 * HID + lane], b01 = g_bufA[u0 * HID + 32 + lane];
        float b10 = g_bufA[u1 * HID + lane], b11 = g_bufA[u1 * HID + 32 + lane];
        float b20 = g_bufA[u2 * HID + lane], b21 = g_bufA[u2 * HID + 32 + lane];
        float b30 = g_bufA[u3 * HID + lane], b31 = g_bufA[u3 * HID + 32 + lane];
        a0 += (b00 + b10) + (b20 + b30);
        a1 += (b01 + b11) + (b21 + b31);
    }
    for (; e < end; e++) {
        int u = g_csr[e];
        a0 += g_bufA[u * HID + lane];
        a1 += g_bufA[u * HID + 32 + lane];
    }
    float s = g_dinv[w];
    float r0 = a0 * s + bias[lane];
    float r1 = a1 * s + bias[32 + lane];
    if (do_relu) { r0 = fmaxf(r0, 0.f); r1 = fmaxf(r1, 0.f); }
    g_bufB[w * HID + lane]      = r0;
    g_bufB[w * HID + 32 + lane] = r1;
}

// pooling + final linear over g_bufB: one block per graph
__global__ void k_pool(const float* __restrict__ Wl, const float* __restrict__ bl,
                       float* __restrict__ outp) {
    __shared__ float sh[256];
    int gph = blockIdx.x;
    int t = threadIdx.x;
    int s = g_goff[gph];
    int c = g_gcnt[gph];
    int d = t & 63, grp = t >> 6;
    float acc = 0.f;
    for (int i = grp; i < c; i += 4) acc += g_bufB[(s + i) * HID + d];
    sh[t] = acc;
    __syncthreads();
    if (t < 64) {
        float p = sh[t] + sh[64 + t] + sh[128 + t] + sh[192 + t];
        p *= 1.0f / fmaxf((float)c, 1.0f);
        sh[t] = p;
    }
    __syncthreads();
    if (t < 2) {
        float o = bl[t];
        #pragma unroll 8
        for (int dd = 0; dd < HID; dd++) o += sh[dd] * Wl[dd * 2 + t];
        outp[gph * 2 + t] = o;
    }
}

// ---------------- launch ---------------------------------------------------
extern "C" void kernel_launch(void* const* d_in, const int* in_sizes, int n_in,
                              void* d_out, int out_size) {
    const float* x     = (const float*)d_in[0];
    const int*   ei    = (const int*)d_in[1];    // int64 in reference -> int32 in harness
    const int*   batch = (const int*)d_in[2];
    const float* W1 = (const float*)d_in[3];
    const float* b1 = (const float*)d_in[4];
    const float* W2 = (const float*)d_in[5];
    const float* b2 = (const float*)d_in[6];
    const float* W3 = (const float*)d_in[7];
    const float* b3 = (const float*)d_in[8];
    const float* Wl = (const float*)d_in[9];
    const float* bl = (const float*)d_in[10];
    float* out = (float*)d_out;

    const int TB = 256;
    int nbN = (N_NODES + TB - 1) / TB;     // 391
    int nbE = (N_EDGES + TB - 1) / TB;     // 4883

    // CSR build + dinv + graph offsets
    k_zero<<<nbN, TB>>>();
    k_deg<<<nbE, TB>>>(ei);
    k_dinv<<<nbN, TB>>>(batch);
    k_scan1<<<SCAN_B, 256>>>();
    k_scan2<<<1, 1>>>();
    k_scan3<<<nbN, TB>>>();
    k_scatter<<<nbE, TB>>>(ei);

    int nbWarp = (N_NODES + 7) / 8;        // 12500 blocks (8 warps each)
    int nbTile = (N_NODES + 63) / 64;      // 1563

    // layer 1
    k_xw1<<<nbWarp, 256>>>(x, W1);
    k_agg<<<nbWarp, 256>>>(b1, 1);
    // layer 2
    k_xw64<<<nbTile, 256>>>(W2);
    k_agg<<<nbWarp, 256>>>(b2, 1);
    // layer 3
    k_xw64<<<nbTile, 256>>>(W3);
    k_agg<<<nbWarp, 256>>>(b3, 0);

    // pooling + classifier
    k_pool<<<NGRAPH, 256>>>(Wl, bl, out);
}

// round 4
// speedup vs baseline: 1.1396x; 1.1396x over previous
#include <cuda_runtime.h>

#define N_NODES 100000
#define N_EDGES 1250000
#define NGRAPH  256
#define HID     64
#define IN_DIM  7

#define SCAN_E  1024
#define SCAN_B  ((N_NODES + SCAN_E - 1) / SCAN_E)   // 98

// ---------------- scratch (device globals; no allocation allowed) ----------
__device__ float g_dinv[N_NODES];
__device__ int   g_deg[N_NODES];
__device__ int   g_rowptr[N_NODES + 1];
__device__ int   g_cursor[N_NODES];
__device__ int   g_csr[N_EDGES];
__device__ int   g_partials[SCAN_B];
__device__ __align__(16) float g_bufA[N_NODES * HID];
__device__ __align__(16) float g_bufB[N_NODES * HID];

// ---------------- setup kernels -------------------------------------------
__global__ void k_zero() {
    int i = blockIdx.x * blockDim.x + threadIdx.x;
    if (i < N_NODES) g_deg[i] = 0;
}

__global__ void k_deg(const int* __restrict__ ei) {
    int e = blockIdx.x * blockDim.x + threadIdx.x;
    if (e < N_EDGES) atomicAdd(&g_deg[ei[N_EDGES + e]], 1);
}

// exclusive scan of g_deg -> g_rowptr (block-local), partial sums to g_partials
__global__ void k_scan1() {
    __shared__ int wraw[8], wscan[8];
    int t = threadIdx.x, b = blockIdx.x;
    int base = b * SCAN_E + t * 4;
    int v0 = 0, v1 = 0, v2 = 0, v3 = 0;
    if (base + 0 < N_NODES) v0 = g_deg[base + 0];
    if (base + 1 < N_NODES) v1 = g_deg[base + 1];
    if (base + 2 < N_NODES) v2 = g_deg[base + 2];
    if (base + 3 < N_NODES) v3 = g_deg[base + 3];
    int ts = v0 + v1 + v2 + v3;
    int lane = t & 31, wid = t >> 5;
    int inc = ts;
    #pragma unroll
    for (int o = 1; o < 32; o <<= 1) {
        int y = __shfl_up_sync(0xffffffffu, inc, o);
        if (lane >= o) inc += y;
    }
    if (lane == 31) wraw[wid] = inc;
    __syncthreads();
    if (t < 8) {
        int w = wraw[t];
        #pragma unroll
        for (int o = 1; o < 8; o <<= 1) {
            int y = __shfl_up_sync(0xffu, w, o);
            if (t >= o) w += y;
        }
        wscan[t] = w;
    }
    __syncthreads();
    int ex = (wid ? wscan[wid - 1] : 0) + (inc - ts);
    if (base + 0 < N_NODES) g_rowptr[base + 0] = ex;  ex += v0;
    if (base + 1 < N_NODES) g_rowptr[base + 1] = ex;  ex += v1;
    if (base + 2 < N_NODES) g_rowptr[base + 2] = ex;  ex += v2;
    if (base + 3 < N_NODES) g_rowptr[base + 3] = ex;
    if (t == 0) g_partials[b] = wscan[7];
}

// warp-parallel exclusive scan of the 98 block partials
__global__ void k_scan2() {
    int lane = threadIdx.x;            // 32 threads
    int base = lane * 4;
    int v0 = (base + 0 < SCAN_B) ? g_partials[base + 0] : 0;
    int v1 = (base + 1 < SCAN_B) ? g_partials[base + 1] : 0;
    int v2 = (base + 2 < SCAN_B) ? g_partials[base + 2] : 0;
    int v3 = (base + 3 < SCAN_B) ? g_partials[base + 3] : 0;
    int ts = v0 + v1 + v2 + v3;
    int inc = ts;
    #pragma unroll
    for (int o = 1; o < 32; o <<= 1) {
        int y = __shfl_up_sync(0xffffffffu, inc, o);
        if (lane >= o) inc += y;
    }
    int ex = inc - ts;
    if (base + 0 < SCAN_B) g_partials[base + 0] = ex;  ex += v0;
    if (base + 1 < SCAN_B) g_partials[base + 1] = ex;  ex += v1;
    if (base + 2 < SCAN_B) g_partials[base + 2] = ex;  ex += v2;
    if (base + 3 < SCAN_B) g_partials[base + 3] = ex;
}

// finalize rowptr, init cursor, compute dinv
__global__ void k_scan3() {
    int i = blockIdx.x * blockDim.x + threadIdx.x;
    if (i < N_NODES) {
        int r = g_rowptr[i] + g_partials[i / SCAN_E];
        g_rowptr[i] = r;
        g_cursor[i] = r;
        g_dinv[i] = rsqrtf((float)(g_deg[i] + 1));   // +1 self-loop
    }
    if (i == 0) g_rowptr[N_NODES] = N_EDGES;
}

__global__ void k_scatter(const int* __restrict__ ei) {
    int e = blockIdx.x * blockDim.x + threadIdx.x;
    if (e < N_EDGES) {
        int d = ei[N_EDGES + e];
        int p = atomicAdd(&g_cursor[d], 1);
        g_csr[p] = ei[e];
    }
}

// ---------------- layer 1 (aggregate 7-dim x first, then GEMM) -------------
// gx[i] = x[i] * dinv[i/7]   -> g_bufB[0 .. N*7)
__global__ void k_gx(const float* __restrict__ x) {
    int i = blockIdx.x * blockDim.x + threadIdx.x;
    if (i < N_NODES * IN_DIM) g_bufB[i] = x[i] * g_dinv[i / IN_DIM];
}

// aggx[v] = dinv[v] * (gx[v] + sum_{CSR[v]} gx[u])   bufB -> bufA  (7 dims)
__global__ void __launch_bounds__(256) k_agg7() {
    int w = (blockIdx.x * blockDim.x + threadIdx.x) >> 5;
    if (w >= N_NODES) return;
    int lane = threadIdx.x & 31;
    int grp = lane / IN_DIM, dim = lane % IN_DIM;     // grp 0..3 active, 4 idle
    float acc = 0.f;
    if (grp == 0) acc = g_bufB[w * IN_DIM + dim];     // self term
    if (grp < 4) {
        int beg = g_rowptr[w], end = g_rowptr[w + 1];
        for (int e = beg + grp; e < end; e += 4) {
            int u = g_csr[e];
            acc += g_bufB[u * IN_DIM + dim];
        }
    }
    __syncwarp();
    acc += __shfl_down_sync(0xffffffffu, acc, 14);
    acc += __shfl_down_sync(0xffffffffu, acc, 7);
    if (lane < IN_DIM) g_bufA[w * IN_DIM + lane] = acc * g_dinv[w];
}

// H1 = relu(aggx @ W1 + b1)   bufA -> bufB   (warp per node)
__global__ void k_h1(const float* __restrict__ W1, const float* __restrict__ b1) {
    __shared__ float sW[IN_DIM * HID];
    int t = threadIdx.x;
    for (int i = t; i < IN_DIM * HID; i += 256) sW[i] = W1[i];
    __syncthreads();
    int w = blockIdx.x * 8 + (t >> 5);
    if (w >= N_NODES) return;
    int lane = t & 31;
    float xv = (lane < IN_DIM) ? g_bufA[w * IN_DIM + lane] : 0.f;
    float a0 = b1[lane], a1 = b1[32 + lane];
    #pragma unroll
    for (int k = 0; k < IN_DIM; k++) {
        float xk = __shfl_sync(0xffffffffu, xv, k);
        a0 += xk * sW[k * HID + lane];
        a1 += xk * sW[k * HID + 32 + lane];
    }
    g_bufB[w * HID + lane]      = fmaxf(a0, 0.f);
    g_bufB[w * HID + 32 + lane] = fmaxf(a1, 0.f);
}

// ---------------- 64-dim layers --------------------------------------------
// 64x64 GEMM tile: g_bufA = dinv[v] * (g_bufB[v] @ W), 64 nodes per block
__global__ void __launch_bounds__(256) k_xw64(const float* __restrict__ W) {
    __shared__ __align__(16) float sA[64][68];  // sA[k][m]
    __shared__ __align__(16) float sW[64][68];  // sW[k][n]
    int t = threadIdx.x;
    int nb = blockIdx.x * 64;
    for (int i = t; i < 4096; i += 256) {
        int k = i >> 6, n = i & 63;
        sW[k][n] = W[i];
        int m = i >> 6, kk = i & 63;
        int node = nb + m;
        sA[kk][m] = (node < N_NODES) ? g_bufB[node * HID + kk] : 0.f;
    }
    __syncthreads();
    int tx = t & 15, ty = t >> 4;
    float acc[4][4] = {};
    #pragma unroll
    for (int k = 0; k < 64; k++) {
        float4 a = *(const float4*)&sA[k][ty * 4];
        float4 wv = *(const float4*)&sW[k][tx * 4];
        acc[0][0] += a.x * wv.x; acc[0][1] += a.x * wv.y; acc[0][2] += a.x * wv.z; acc[0][3] += a.x * wv.w;
        acc[1][0] += a.y * wv.x; acc[1][1] += a.y * wv.y; acc[1][2] += a.y * wv.z; acc[1][3] += a.y * wv.w;
        acc[2][0] += a.z * wv.x; acc[2][1] += a.z * wv.y; acc[2][2] += a.z * wv.z; acc[2][3] += a.z * wv.w;
        acc[3][0] += a.w * wv.x; acc[3][1] += a.w * wv.y; acc[3][2] += a.w * wv.z; acc[3][3] += a.w * wv.w;
    }
    #pragma unroll
    for (int m = 0; m < 4; m++) {
        int node = nb + ty * 4 + m;
        if (node < N_NODES) {
            float s = g_dinv[node];
            float4 r;
            r.x = acc[m][0] * s; r.y = acc[m][1] * s; r.z = acc[m][2] * s; r.w = acc[m][3] * s;
            *(float4*)&g_bufA[node * HID + tx * 4] = r;
        }
    }
}

// aggregation: bufB[v] = act( dinv[v]*(bufA[v] + sum gather) + bias )
// half-warp float4 scheme: each half covers all 64 dims; halves split edges.
__global__ void __launch_bounds__(256) k_agg(const float* __restrict__ bias, int do_relu) {
    int w = (blockIdx.x * blockDim.x + threadIdx.x) >> 5;
    if (w >= N_NODES) return;
    int lane = threadIdx.x & 31;
    int half = lane >> 4, sub = lane & 15;
    const float4* inA = (const float4*)g_bufA;
    float4 acc;
    if (half == 0) acc = inA[w * 16 + sub];               // self term once
    else           acc = make_float4(0.f, 0.f, 0.f, 0.f);
    int beg = g_rowptr[w], end = g_rowptr[w + 1];
    int e = beg + half;
    for (; e + 2 < end; e += 4) {                          // unroll 2 (stride 2/half)
        int u0 = g_csr[e], u1 = g_csr[e + 2];
        float4 b0 = inA[u0 * 16 + sub];
        float4 b1 = inA[u1 * 16 + sub];
        acc.x += b0.x + b1.x; acc.y += b0.y + b1.y;
        acc.z += b0.z + b1.z; acc.w += b0.w + b1.w;
    }
    for (; e < end; e += 2) {
        int u = g_csr[e];
        float4 b = inA[u * 16 + sub];
        acc.x += b.x; acc.y += b.y; acc.z += b.z; acc.w += b.w;
    }
    __syncwarp();
    acc.x += __shfl_down_sync(0xffffffffu, acc.x, 16);
    acc.y += __shfl_down_sync(0xffffffffu, acc.y, 16);
    acc.z += __shfl_down_sync(0xffffffffu, acc.z, 16);
    acc.w += __shfl_down_sync(0xffffffffu, acc.w, 16);
    if (half == 0) {
        float s = g_dinv[w];
        float4 bb = ((const float4*)bias)[sub];
        float4 r;
        r.x = acc.x * s + bb.x; r.y = acc.y * s + bb.y;
        r.z = acc.z * s + bb.z; r.w = acc.w * s + bb.w;
        if (do_relu) {
            r.x = fmaxf(r.x, 0.f); r.y = fmaxf(r.y, 0.f);
            r.z = fmaxf(r.z, 0.f); r.w = fmaxf(r.w, 0.f);
        }
        ((float4*)g_bufB)[w * 16 + sub] = r;
    }
}

// pooling + final linear over g_bufB; graph ranges via binary search on batch
__global__ void k_pool(const int* __restrict__ batch,
                       const float* __restrict__ Wl, const float* __restrict__ bl,
                       float* __restrict__ outp) {
    __shared__ float sh[256];
    int gph = blockIdx.x;
    int t = threadIdx.x;
    int lo = 0, hi = N_NODES;
    while (lo < hi) { int mid = (lo + hi) >> 1; if (batch[mid] < gph) lo = mid + 1; else hi = mid; }
    int s = lo;
    hi = N_NODES;
    while (lo < hi) { int mid = (lo + hi) >> 1; if (batch[mid] < gph + 1) lo = mid + 1; else hi = mid; }
    int c = lo - s;
    int d = t & 63, grp = t >> 6;
    float acc = 0.f;
    for (int i = grp; i < c; i += 4) acc += g_bufB[(s + i) * HID + d];
    sh[t] = acc;
    __syncthreads();
    if (t < 64) {
        float p = sh[t] + sh[64 + t] + sh[128 + t] + sh[192 + t];
        p *= 1.0f / fmaxf((float)c, 1.0f);
        sh[t] = p;
    }
    __syncthreads();
    if (t < 2) {
        float o = bl[t];
        #pragma unroll 8
        for (int dd = 0; dd < HID; dd++) o += sh[dd] * Wl[dd * 2 + t];
        outp[gph * 2 + t] = o;
    }
}

// ---------------- launch ---------------------------------------------------
extern "C" void kernel_launch(void* const* d_in, const int* in_sizes, int n_in,
                              void* d_out, int out_size) {
    const float* x     = (const float*)d_in[0];
    const int*   ei    = (const int*)d_in[1];    // int64 in reference -> int32 in harness
    const int*   batch = (const int*)d_in[2];
    const float* W1 = (const float*)d_in[3];
    const float* b1 = (const float*)d_in[4];
    const float* W2 = (const float*)d_in[5];
    const float* b2 = (const float*)d_in[6];
    const float* W3 = (const float*)d_in[7];
    const float* b3 = (const float*)d_in[8];
    const float* Wl = (const float*)d_in[9];
    const float* bl = (const float*)d_in[10];
    float* out = (float*)d_out;

    const int TB = 256;
    int nbN = (N_NODES + TB - 1) / TB;                 // 391
    int nbE = (N_EDGES + TB - 1) / TB;                 // 4883
    int nbX = (N_NODES * IN_DIM + TB - 1) / TB;        // 2735
    int nbWarp = (N_NODES + 7) / 8;                    // 12500
    int nbTile = (N_NODES + 63) / 64;                  // 1563

    // CSR build + dinv
    k_zero<<<nbN, TB>>>();
    k_deg<<<nbE, TB>>>(ei);
    k_scan1<<<SCAN_B, 256>>>();
    k_scan2<<<1, 32>>>();
    k_scan3<<<nbN, TB>>>();
    k_scatter<<<nbE, TB>>>(ei);

    // layer 1 (aggregate 7-dim input first)
    k_gx<<<nbX, TB>>>(x);
    k_agg7<<<nbWarp, 256>>>();
    k_h1<<<nbWarp, 256>>>(W1, b1);
    // layer 2
    k_xw64<<<nbTile, 256>>>(W2);
    k_agg<<<nbWarp, 256>>>(b2, 1);
    // layer 3
    k_xw64<<<nbTile, 256>>>(W3);
    k_agg<<<nbWarp, 256>>>(b3, 0);

    // pooling + classifier
    k_pool<<<NGRAPH, 256>>>(batch, Wl, bl, out);
}